// round 17
// baseline (speedup 1.0000x reference)
#include <cuda_runtime.h>
#include <cuda_fp16.h>
#include <cstdint>

// ---------------------------------------------------------------------------
// Problem constants
// ---------------------------------------------------------------------------
#define OUT_N    8192
#define IN_K     8192
#define BATCH    64
#define TILE_N   128                  // W rows per CTA
#define KSPLIT   8
#define NGRPS    (OUT_N / TILE_N)     // 64
#define NSUB     16                   // k64 subchunks per CTA (k total 1024)
#define NCH      8                    // k128 scale-chunks per CTA
#define NTHREADS 256

// SMEM layout. Row stride 144 B (128 data + 16 pad; 144 ≡ 16 mod 128 makes
// both the per-lane B LDS.U32 pattern and the x ldmatrix pattern bank-clean).
#define RS          144
#define WR_BYTES    (TILE_N * RS)          // 18432 raw packed W (int32 view)
#define X_BYTES     (BATCH * RS)           // 9216
#define X_OFF       (2 * WR_BYTES)         // 36864
#define SCALE_OFF   (X_OFF + 2 * X_BYTES)  // 55296
#define SCALE_BYTES (NCH * TILE_N * 4)     // 4096 (half2-packed per entry)
#define SMEM_TOTAL  (SCALE_OFF + SCALE_BYTES)  // 59392 -> 3 CTAs/SM

// Static scratch: x converted to fp16 (1 MiB)
__device__ __half g_xh[BATCH * IN_K];

// ---------------------------------------------------------------------------
// PTX helpers (family-portable: ptxas target is sm_103, no tcgen05)
// ---------------------------------------------------------------------------
__device__ __forceinline__ void ldsm_x4(uint32_t& r0, uint32_t& r1, uint32_t& r2,
                                        uint32_t& r3, uint32_t addr) {
    asm volatile("ldmatrix.sync.aligned.m8n8.x4.shared.b16 {%0,%1,%2,%3}, [%4];"
                 : "=r"(r0), "=r"(r1), "=r"(r2), "=r"(r3) : "r"(addr));
}
__device__ __forceinline__ void mma_16816(float* c, uint32_t a0, uint32_t a1,
                                          uint32_t a2, uint32_t a3,
                                          uint32_t b0, uint32_t b1) {
    asm volatile(
        "mma.sync.aligned.m16n8k16.row.col.f32.f16.f16.f32 "
        "{%0,%1,%2,%3},{%4,%5,%6,%7},{%8,%9},{%0,%1,%2,%3};"
        : "+f"(c[0]), "+f"(c[1]), "+f"(c[2]), "+f"(c[3])
        : "r"(a0), "r"(a1), "r"(a2), "r"(a3), "r"(b0), "r"(b1));
}
__device__ __forceinline__ uint32_t lds_u32(uint32_t addr) {
    uint32_t v;
    asm volatile("ld.shared.b32 %0, [%1];" : "=r"(v) : "r"(addr));
    return v;
}
// x tile: co-resident CTAs re-read identical windows -> keep in L1 (.ca)
__device__ __forceinline__ void cp_async16_ca(uint32_t dst, const void* src) {
    asm volatile("cp.async.ca.shared.global [%0], [%1], 16;"
                 :: "r"(dst), "l"(src) : "memory");
}
// W raw: zero-reuse stream -> bypass L1 (.cg), don't evict x windows
__device__ __forceinline__ void cp_async16_cg(uint32_t dst, const void* src) {
    asm volatile("cp.async.cg.shared.global [%0], [%1], 16;"
                 :: "r"(dst), "l"(src) : "memory");
}
__device__ __forceinline__ void cp_commit() {
    asm volatile("cp.async.commit_group;" ::: "memory");
}

// exact int4 dequant: nibble pair -> half2, (q-8)*scale with single rounding
__device__ __forceinline__ uint32_t dq_pair(uint32_t w, __half2 s2, __half2 c1032) {
    uint32_t t = ((w * 0x1001u) & 0x000F000Fu) | 0x64006400u;
    __half2 hv = __hmul2(__hsub2(*reinterpret_cast<__half2*>(&t), c1032), s2);
    return *reinterpret_cast<uint32_t*>(&hv);
}

// ---------------------------------------------------------------------------
// Kernel 1: convert x fp32->fp16 AND zero-init out.
// ---------------------------------------------------------------------------
__global__ __launch_bounds__(256) void prep_kernel(const float* __restrict__ x,
                                                   float* __restrict__ out) {
    int base = blockIdx.x * 512 + threadIdx.x;
    #pragma unroll
    for (int k = 0; k < 2; k++) {
        int i = base + k * 256;
        float4 v = reinterpret_cast<const float4*>(x)[i];
        __half2 h01 = __floats2half2_rn(v.x, v.y);
        __half2 h23 = __floats2half2_rn(v.z, v.w);
        uint2 o;
        o.x = *reinterpret_cast<uint32_t*>(&h01);
        o.y = *reinterpret_cast<uint32_t*>(&h23);
        reinterpret_cast<uint2*>(g_xh)[i] = o;
        reinterpret_cast<float4*>(out)[i] = make_float4(0.f, 0.f, 0.f, 0.f);
    }
}

// ---------------------------------------------------------------------------
// Kernel 2: int4-dequant GEMM with IN-REGISTER B fragments.
// Grid = 512 CTAs: bid & 63 = n-group (128 W rows), bid >> 6 = k-group.
// Warp layout 2(m) x 4(n). W raw packed is staged via cp.async (16KB/sub,
// same bytes as the old fp16 tile thanks to int32 inflation) and each lane
// builds its B frags directly: b0 needs exactly packed int32 (k-pair) at
// element (lane&3), b1 at (lane&3)+4 of the kt-group -> 2 conflict-free
// LDS.U32 + 4-op dequant per (nt,kt). No W STS, no B ldsm.
// ---------------------------------------------------------------------------
__global__ __launch_bounds__(NTHREADS, 3)
void dq_gemm_kernel(const int*   __restrict__ packed,
                    const float* __restrict__ scales,
                    float*       __restrict__ out)
{
    extern __shared__ __align__(16) char dsm[];
    const uint32_t sb = (uint32_t)__cvta_generic_to_shared(dsm);

    const int tid  = threadIdx.x;
    const int wid  = tid >> 5;
    const int lane = tid & 31;
    const int mh   = wid & 1;          // batch half
    const int ng   = wid >> 1;         // 32-col group
    const int n0   = (blockIdx.x & 63) * TILE_N;
    const int kg   = blockIdx.x >> 6;  // 0..7
    const int ks0  = kg * NSUB;        // global k64-subchunk base

    float acc[2][4][4];
    #pragma unroll
    for (int m = 0; m < 2; m++)
        #pragma unroll
        for (int n = 0; n < 4; n++)
            #pragma unroll
            for (int j = 0; j < 4; j++) acc[m][n][j] = 0.f;

    const uint32_t c1032b = 0x64086408u;              // half2(1032,1032)
    const __half2 c1032 = *reinterpret_cast<const __half2*>(&c1032b);

    // ---- scale table, half2-packed: [NCH][TILE_N] -------------------------
    {
        int row = tid >> 1;                      // 0..127
        int c4  = tid & 1;
        float4 f = *reinterpret_cast<const float4*>(
            scales + (size_t)(n0 + row) * 64 + kg * NCH + c4 * 4);
        uint32_t* sc = reinterpret_cast<uint32_t*>(dsm + SCALE_OFF);
        float fv[4] = { f.x, f.y, f.z, f.w };
        #pragma unroll
        for (int q = 0; q < 4; q++) {
            __half2 h2 = __float2half2_rn(fv[q]);
            sc[(c4 * 4 + q) * TILE_N + row] = *reinterpret_cast<uint32_t*>(&h2);
        }
    }

    // ---- W raw cp.async (1024 x 16B = 4/thread), L2-only ------------------
    auto stage_w = [&](int ks, int s) {
        const uint32_t wb = sb + s * WR_BYTES;
        #pragma unroll
        for (int j = 0; j < 4; j++) {
            int u = tid + (j << 8);              // 0..1023
            int r = u >> 3, e = u & 7;           // row, 16B unit (4 int32)
            cp_async16_cg(wb + r * RS + e * 16,
                          packed + (size_t)(n0 + r) * 4096 + ks * 32 + e * 4);
        }
    };

    // ---- x tile cp.async (512 x 16B = 2/thread), L1-cached ----------------
    auto stage_x = [&](int ks, int s) {
        const uint32_t xb = sb + X_OFF + s * X_BYTES;
        #pragma unroll
        for (int j = 0; j < 2; j++) {
            int u = tid + (j << 8);              // 0..511
            int b = u >> 3, kv = u & 7;
            cp_async16_ca(xb + b * RS + kv * 16,
                          &g_xh[(size_t)b * IN_K + ks * 64 + kv * 8]);
        }
    };

    // ---- prologue ---------------------------------------------------------
    stage_w(ks0, 0);
    stage_x(ks0, 0);
    cp_commit();

    // per-lane B addressing constants
    const uint32_t bq  = (uint32_t)(lane & 3) * 4;    // int32 sel within kt-group
    const uint32_t brw = (uint32_t)(lane >> 2);       // row within n8 tile

    // Invariant at iteration entry (sub, s = sub&1):
    //   W-raw[sub] + x[sub] are the pending cp.async group (stage s).
    for (int sub = 0; sub < NSUB; sub++) {
        const int s = sub & 1;

        asm volatile("cp.async.wait_group 0;" ::: "memory");  // sub's data landed
        __syncthreads();     // stage s readable; stage s^1 free of readers
                             // (also orders the prologue scale-table writes)

        if (sub + 1 < NSUB) {
            stage_w(ks0 + sub + 1, s ^ 1);
            stage_x(ks0 + sub + 1, s ^ 1);
            cp_commit();
        }

        const uint32_t wb = sb + s * WR_BYTES;
        const uint32_t xb = sb + X_OFF + s * X_BYTES;

        // scales for this sub (k128 chunk = sub>>1), one half2 per nt
        __half2 s2[4];
        {
            const uint32_t scb = sb + SCALE_OFF + (uint32_t)((sub >> 1) * TILE_N) * 4;
            #pragma unroll
            for (int nt = 0; nt < 4; nt++) {
                uint32_t v = lds_u32(scb + (uint32_t)(ng * 32 + nt * 8 + brw) * 4);
                s2[nt] = *reinterpret_cast<__half2*>(&v);
            }
        }

        // ---- MMA(sub): 4 k16 tiles; B frags built in registers ------------
        #pragma unroll
        for (int kt = 0; kt < 4; kt++) {
            uint32_t a[2][4];
            #pragma unroll
            for (int mt = 0; mt < 2; mt++) {
                int ar = mh * 32 + mt * 16 + (lane & 15);
                int ac = kt * 16 + (lane >> 4) * 8;
                ldsm_x4(a[mt][0], a[mt][1], a[mt][2], a[mt][3],
                        xb + (uint32_t)(ar * RS + ac * 2));
            }
            #pragma unroll
            for (int nt = 0; nt < 4; nt++) {
                // lane's packed int32s: row r, elements kt*8+(lane&3), +4
                uint32_t addr = wb + (uint32_t)(ng * 32 + nt * 8 + brw) * RS
                              + (uint32_t)(kt * 32) + bq;
                uint32_t w0 = lds_u32(addr);
                uint32_t w1 = lds_u32(addr + 16);
                uint32_t b0 = dq_pair(w0, s2[nt], c1032);
                uint32_t b1 = dq_pair(w1, s2[nt], c1032);
                mma_16816(acc[0][nt], a[0][0], a[0][1], a[0][2], a[0][3], b0, b1);
                mma_16816(acc[1][nt], a[1][0], a[1][1], a[1][2], a[1][3], b0, b1);
            }
        }
    }

    // ---- epilogue: vectorized float2 atomics (k-split merge) --------------
    #pragma unroll
    for (int mt = 0; mt < 2; mt++) {
        #pragma unroll
        for (int nt = 0; nt < 4; nt++) {
            int m = mh * 32 + mt * 16 + (lane >> 2);
            int n = n0 + ng * 32 + nt * 8 + (lane & 3) * 2;
            atomicAdd(reinterpret_cast<float2*>(&out[(size_t)m * OUT_N + n]),
                      make_float2(acc[mt][nt][0], acc[mt][nt][1]));
            atomicAdd(reinterpret_cast<float2*>(&out[(size_t)(m + 8) * OUT_N + n]),
                      make_float2(acc[mt][nt][2], acc[mt][nt][3]));
        }
    }
}

// ---------------------------------------------------------------------------
extern "C" void kernel_launch(void* const* d_in, const int* in_sizes, int n_in,
                              void* d_out, int out_size) {
    const float* x      = (const float*)d_in[0];
    const int*   packed = (const int*)d_in[1];
    const float* scales = (const float*)d_in[2];
    float*       out    = (float*)d_out;

    cudaFuncSetAttribute(dq_gemm_kernel,
                         cudaFuncAttributeMaxDynamicSharedMemorySize, SMEM_TOTAL);

    prep_kernel<<<256, 256>>>(x, out);
    dq_gemm_kernel<<<NGRPS * KSPLIT, NTHREADS, SMEM_TOTAL>>>(packed, scales, out);
}